// round 1
// baseline (speedup 1.0000x reference)
#include <cuda_runtime.h>

typedef unsigned long long ull;

static constexpr int Bn = 2;
static constexpr int Ln = 2048;
static constexpr int Dn = 1536;
static constexpr int BM = 128;
static constexpr int BK = 16;
static constexpr int NTILE = Ln / BM;              // 16
static constexpr int NPAIR = NTILE * (NTILE + 1) / 2;  // 136

__device__ __forceinline__ ull pack2(float x) {
    ull r;
    unsigned u = __float_as_uint(x);
    asm("mov.b64 %0, {%1, %1};" : "=l"(r) : "r"(u));
    return r;
}

__device__ __forceinline__ void fma2(ull &d, ull a, ull b) {
    asm("fma.rn.f32x2 %0, %1, %2, %0;" : "+l"(d) : "l"(a), "l"(b));
}

__global__ __launch_bounds__(256, 2)
void cph_gram_kernel(const float* __restrict__ H,
                     const float* __restrict__ W,
                     const float* __restrict__ bias,
                     float* __restrict__ out)
{
    __shared__ __align__(16) float As[BK][BM];
    __shared__ __align__(16) float Bs[BK][BM];

    const int tid = threadIdx.x;
    const int tx = tid & 15;        // 0..15 -> n
    const int ty = tid >> 4;        // 0..15 -> m
    const int batch = blockIdx.y;
    const int t = blockIdx.z;

    // decode upper-triangular tile pair (ti <= tj)
    int rem = blockIdx.x;
    int ti = 0;
    int rowlen = NTILE;
    while (rem >= rowlen) { rem -= rowlen; --rowlen; ++ti; }
    const int tj = ti + rem;

    const float* __restrict__ Hb = H + (size_t)batch * Ln * Dn;
    const float* __restrict__ Wp = W + (size_t)t * (2 * Dn);   // first Dn cols = Wp_t
    const float bt = __ldg(&bias[t]);

    const int gi0 = ti * BM;
    const int gj0 = tj * BM;

    ull acc[8][4];
#pragma unroll
    for (int m = 0; m < 8; ++m)
#pragma unroll
        for (int p = 0; p < 4; ++p) acc[m][p] = 0ull;

    const int r0 = tid >> 2;          // 0..63
    const int cg = (tid & 3) * 4;     // 0,4,8,12

    for (int kt = 0; kt < Dn; kt += BK) {
        const float4 wv = *reinterpret_cast<const float4*>(Wp + kt + cg);
#pragma unroll
        for (int l = 0; l < 2; ++l) {
            const int r = r0 + l * 64;
            const float4 av = *reinterpret_cast<const float4*>(
                Hb + (size_t)(gi0 + r) * Dn + kt + cg);
            As[cg + 0][r] = av.x * wv.x;
            As[cg + 1][r] = av.y * wv.y;
            As[cg + 2][r] = av.z * wv.z;
            As[cg + 3][r] = av.w * wv.w;
            const float4 bv = *reinterpret_cast<const float4*>(
                Hb + (size_t)(gj0 + r) * Dn + kt + cg);
            Bs[cg + 0][r] = bv.x;
            Bs[cg + 1][r] = bv.y;
            Bs[cg + 2][r] = bv.z;
            Bs[cg + 3][r] = bv.w;
        }
        __syncthreads();

#pragma unroll
        for (int kk = 0; kk < BK; ++kk) {
            const float4 alo = *reinterpret_cast<const float4*>(&As[kk][ty * 4]);
            const float4 ahi = *reinterpret_cast<const float4*>(&As[kk][64 + ty * 4]);
            const ulonglong2 bl = *reinterpret_cast<const ulonglong2*>(&Bs[kk][tx * 4]);
            const ulonglong2 bh = *reinterpret_cast<const ulonglong2*>(&Bs[kk][64 + tx * 4]);
            ull a2[8];
            a2[0] = pack2(alo.x); a2[1] = pack2(alo.y);
            a2[2] = pack2(alo.z); a2[3] = pack2(alo.w);
            a2[4] = pack2(ahi.x); a2[5] = pack2(ahi.y);
            a2[6] = pack2(ahi.z); a2[7] = pack2(ahi.w);
            ull b2[4] = { bl.x, bl.y, bh.x, bh.y };
#pragma unroll
            for (int m = 0; m < 8; ++m)
#pragma unroll
                for (int p = 0; p < 4; ++p)
                    fma2(acc[m][p], a2[m], b2[p]);
        }
        __syncthreads();
    }

    // epilogue: out[((batch*L + i)*L + j)*2 + t], plus mirrored tile if ti != tj
    float* __restrict__ outB = out + (size_t)batch * Ln * Ln * 2 + t;

#pragma unroll
    for (int m = 0; m < 8; ++m) {
        const int gi = gi0 + ((m < 4) ? (ty * 4 + m) : (64 + ty * 4 + (m - 4)));
        float v[8];
#pragma unroll
        for (int p = 0; p < 4; ++p) {
            unsigned lo, hi;
            asm("mov.b64 {%0, %1}, %2;" : "=r"(lo), "=r"(hi) : "l"(acc[m][p]));
            v[2 * p]     = __uint_as_float(lo) + bt;
            v[2 * p + 1] = __uint_as_float(hi) + bt;
        }
#pragma unroll
        for (int e = 0; e < 8; ++e) {
            const int gj = gj0 + ((e < 4) ? (tx * 4 + e) : (64 + tx * 4 + (e - 4)));
            outB[((size_t)gi * Ln + gj) * 2] = v[e];
            if (ti != tj)
                outB[((size_t)gj * Ln + gi) * 2] = v[e];
        }
    }
}

extern "C" void kernel_launch(void* const* d_in, const int* in_sizes, int n_in,
                              void* d_out, int out_size)
{
    const float* H    = (const float*)d_in[0];
    const float* W    = (const float*)d_in[1];
    const float* bias = (const float*)d_in[2];
    float* out = (float*)d_out;

    dim3 grid(NPAIR, Bn, 2);   // tile-pairs x batch x t
    cph_gram_kernel<<<grid, 256>>>(H, W, bias, out);
}

// round 3
// speedup vs baseline: 2.2870x; 2.2870x over previous
#include <cuda_runtime.h>
#include <cuda_bf16.h>
#include <cstdint>

static constexpr int Bn = 2;
static constexpr int Ln = 2048;
static constexpr int Dn = 1536;
static constexpr int NTILE = Ln / 128;                 // 16
static constexpr int NPAIR = NTILE * (NTILE + 1) / 2;  // 136
static constexpr int BK = 32;                          // k per stage
static constexpr int NSTG = Dn / BK;                   // 48
static constexpr int RS = BK + 8;                      // smem row stride (elems) = 80B
static constexpr int TILE_B = 128 * RS * 2;            // 10240 bytes per tile
static constexpr int SMEM_DYN = 2 * 4 * TILE_B;        // 81920 bytes

// bf16 planes: 0..7 = H*Wp_t split (b*4 + t*2 + {hi,lo}); 8..11 = H split (8 + b*2 + {hi,lo})
__device__ __align__(16) __nv_bfloat16 g_cvt[12ull * Ln * Dn];

// ---------------------------------------------------------------- convert
__global__ __launch_bounds__(256) void cvt_kernel(const float* __restrict__ H,
                                                  const float* __restrict__ W)
{
    const int idx = blockIdx.x * 256 + threadIdx.x;   // Bn*Ln*(Dn/4) total
    const int d4  = idx % (Dn / 4);
    const int row = (idx / (Dn / 4)) % Ln;
    const int b   = idx / ((Dn / 4) * Ln);
    const int d0  = d4 * 4;

    const float4 h = *reinterpret_cast<const float4*>(H + ((size_t)b * Ln + row) * Dn + d0);
    const size_t rowoff = (size_t)row * Dn + d0;

    auto store_split = [&](int plane_hi, float4 v) {
        float a[4] = {v.x, v.y, v.z, v.w};
        __nv_bfloat16 hi[4], lo[4];
#pragma unroll
        for (int i = 0; i < 4; ++i) {
            hi[i] = __float2bfloat16(a[i]);
            lo[i] = __float2bfloat16(a[i] - __bfloat162float(hi[i]));
        }
        __nv_bfloat162* ph = reinterpret_cast<__nv_bfloat162*>(
            g_cvt + (size_t)plane_hi * Ln * Dn + rowoff);
        __nv_bfloat162* pl = reinterpret_cast<__nv_bfloat162*>(
            g_cvt + (size_t)(plane_hi + 1) * Ln * Dn + rowoff);
        ph[0] = __nv_bfloat162(hi[0], hi[1]);
        ph[1] = __nv_bfloat162(hi[2], hi[3]);
        pl[0] = __nv_bfloat162(lo[0], lo[1]);
        pl[1] = __nv_bfloat162(lo[2], lo[3]);
    };

#pragma unroll
    for (int t = 0; t < 2; ++t) {
        const float4 w = *reinterpret_cast<const float4*>(W + (size_t)t * (2 * Dn) + d0);
        store_split(b * 4 + t * 2, make_float4(h.x * w.x, h.y * w.y, h.z * w.z, h.w * w.w));
    }
    store_split(8 + b * 2, h);
}

// ---------------------------------------------------------------- helpers
__device__ __forceinline__ uint32_t s2u(const void* p) {
    uint32_t a;
    asm("{ .reg .u64 t; cvta.to.shared.u64 t, %1; cvt.u32.u64 %0, t; }" : "=r"(a) : "l"(p));
    return a;
}

#define LDSM4(R0, R1, R2, R3, addr)                                            \
    asm volatile("ldmatrix.sync.aligned.m8n8.x4.shared.b16 {%0,%1,%2,%3}, [%4];" \
                 : "=r"(R0), "=r"(R1), "=r"(R2), "=r"(R3) : "r"(addr))

#define MMA(C, A, B)                                                              \
    asm volatile(                                                                 \
        "mma.sync.aligned.m16n8k16.row.col.f32.bf16.bf16.f32 "                    \
        "{%0,%1,%2,%3},{%4,%5,%6,%7},{%8,%9},{%0,%1,%2,%3};"                      \
        : "+f"((C)[0]), "+f"((C)[1]), "+f"((C)[2]), "+f"((C)[3])                  \
        : "r"((A)[0]), "r"((A)[1]), "r"((A)[2]), "r"((A)[3]),                     \
          "r"((B)[0]), "r"((B)[1]))

// ---------------------------------------------------------------- gram GEMM
__global__ __launch_bounds__(256, 2)
void gram_hmma(const float* __restrict__ bias, float* __restrict__ out)
{
    extern __shared__ char smem_raw[];
    const uint32_t sb = s2u(smem_raw);

    const int tid = threadIdx.x;
    const int wid = tid >> 5;
    const int lane = tid & 31;

    // warp tile: 64x32; warp grid 2(m) x 4(n)
    const int wm = (wid >> 2) * 64;
    const int wn = (wid & 3) * 32;

    // ldmatrix lane address components
    const int a_row = (lane & 7) + ((lane >> 3) & 1) * 8;
    const int a_k   = (lane >> 4) * 8;
    const int b_row = (lane & 7) + (lane >> 4) * 8;
    const int b_k   = ((lane >> 3) & 1) * 8;

    // decode upper-triangular tile pair
    int rem = blockIdx.x, ti = 0, rl = NTILE;
    while (rem >= rl) { rem -= rl; --rl; ++ti; }
    const int tj = ti + rem;
    const int b = blockIdx.y;
    const int t = blockIdx.z;
    const int gi0 = ti * 128, gj0 = tj * 128;

    const __nv_bfloat16* src[4];
    src[0] = g_cvt + ((size_t)(b * 4 + t * 2) * Ln + gi0) * Dn;      // A hi
    src[1] = src[0] + (size_t)Ln * Dn;                                // A lo
    src[2] = g_cvt + ((size_t)(8 + b * 2) * Ln + gj0) * Dn;           // B hi
    src[3] = src[2] + (size_t)Ln * Dn;                                // B lo

    auto load_stage = [&](int s, int buf) {
        const int k0 = s * BK;
#pragma unroll
        for (int tI = 0; tI < 4; ++tI) {
            const __nv_bfloat16* base = src[tI] + k0;
            const uint32_t tb = sb + (buf * 4 + tI) * TILE_B;
#pragma unroll
            for (int c2 = 0; c2 < 2; ++c2) {
                const int chunk = tid + 256 * c2;   // 0..511
                const int row = chunk >> 2, part = chunk & 3;
                const uint32_t d = tb + row * (RS * 2) + part * 16;
                const void* g = base + (size_t)row * Dn + part * 8;
                asm volatile("cp.async.cg.shared.global [%0], [%1], 16;"
                             :: "r"(d), "l"(g) : "memory");
            }
        }
    };

    float acc[4][4][4];
#pragma unroll
    for (int mt = 0; mt < 4; ++mt)
#pragma unroll
        for (int nt = 0; nt < 4; ++nt)
#pragma unroll
            for (int e = 0; e < 4; ++e) acc[mt][nt][e] = 0.f;

    load_stage(0, 0);
    asm volatile("cp.async.commit_group;" ::: "memory");

#pragma unroll 1
    for (int s = 0; s < NSTG; ++s) {
        const int buf = s & 1;
        if (s + 1 < NSTG) {
            load_stage(s + 1, buf ^ 1);
            asm volatile("cp.async.commit_group;" ::: "memory");
            asm volatile("cp.async.wait_group 1;" ::: "memory");
        } else {
            asm volatile("cp.async.wait_group 0;" ::: "memory");
        }
        __syncthreads();

        const uint32_t Ah = sb + (buf * 4 + 0) * TILE_B;
        const uint32_t Al = sb + (buf * 4 + 1) * TILE_B;
        const uint32_t Bh = sb + (buf * 4 + 2) * TILE_B;
        const uint32_t Bl = sb + (buf * 4 + 3) * TILE_B;

#pragma unroll
        for (int s16 = 0; s16 < 2; ++s16) {
            const int k0s = s16 * 16;

            uint32_t bh[4][2], bl[4][2];
#pragma unroll
            for (int n2 = 0; n2 < 2; ++n2) {
                uint32_t addr = Bh + ((wn + n2 * 16 + b_row) * RS + k0s + b_k) * 2;
                LDSM4(bh[n2 * 2][0], bh[n2 * 2][1], bh[n2 * 2 + 1][0], bh[n2 * 2 + 1][1], addr);
                addr = Bl + ((wn + n2 * 16 + b_row) * RS + k0s + b_k) * 2;
                LDSM4(bl[n2 * 2][0], bl[n2 * 2][1], bl[n2 * 2 + 1][0], bl[n2 * 2 + 1][1], addr);
            }

            {
                uint32_t ah[4][4];
#pragma unroll
                for (int mt = 0; mt < 4; ++mt) {
                    const uint32_t addr = Ah + ((wm + mt * 16 + a_row) * RS + k0s + a_k) * 2;
                    LDSM4(ah[mt][0], ah[mt][1], ah[mt][2], ah[mt][3], addr);
                }
#pragma unroll
                for (int mt = 0; mt < 4; ++mt)
#pragma unroll
                    for (int nt = 0; nt < 4; ++nt) {
                        MMA(acc[mt][nt], ah[mt], bh[nt]);
                        MMA(acc[mt][nt], ah[mt], bl[nt]);
                    }
            }
            {
                uint32_t al[4][4];
#pragma unroll
                for (int mt = 0; mt < 4; ++mt) {
                    const uint32_t addr = Al + ((wm + mt * 16 + a_row) * RS + k0s + a_k) * 2;
                    LDSM4(al[mt][0], al[mt][1], al[mt][2], al[mt][3], addr);
                }
#pragma unroll
                for (int mt = 0; mt < 4; ++mt)
#pragma unroll
                    for (int nt = 0; nt < 4; ++nt)
                        MMA(acc[mt][nt], al[mt], bh[nt]);
            }
        }
        __syncthreads();
    }

    // ------------------------------------------------------------ epilogue
    const float bt = __ldg(&bias[t]);
    float* o = out + ((size_t)b * Ln * Ln) * 2 + t;
    const int r4 = lane >> 2;
    const int c4 = (lane & 3) * 2;
    const bool mirror = (ti != tj);

#pragma unroll
    for (int mt = 0; mt < 4; ++mt) {
#pragma unroll
        for (int nt = 0; nt < 4; ++nt) {
            const int i0 = gi0 + wm + mt * 16 + r4;
            const int j0 = gj0 + wn + nt * 8 + c4;
            const float v0 = acc[mt][nt][0] + bt;
            const float v1 = acc[mt][nt][1] + bt;
            const float v2 = acc[mt][nt][2] + bt;
            const float v3 = acc[mt][nt][3] + bt;
            o[((size_t)i0 * Ln + j0) * 2]           = v0;
            o[((size_t)i0 * Ln + j0 + 1) * 2]       = v1;
            o[((size_t)(i0 + 8) * Ln + j0) * 2]     = v2;
            o[((size_t)(i0 + 8) * Ln + j0 + 1) * 2] = v3;
            if (mirror) {
                o[((size_t)j0 * Ln + i0) * 2]           = v0;
                o[((size_t)(j0 + 1) * Ln + i0) * 2]     = v1;
                o[((size_t)j0 * Ln + i0 + 8) * 2]       = v2;
                o[((size_t)(j0 + 1) * Ln + i0 + 8) * 2] = v3;
            }
        }
    }
}

// ---------------------------------------------------------------- launch
extern "C" void kernel_launch(void* const* d_in, const int* in_sizes, int n_in,
                              void* d_out, int out_size)
{
    const float* H    = (const float*)d_in[0];
    const float* W    = (const float*)d_in[1];
    const float* bias = (const float*)d_in[2];
    float* out = (float*)d_out;

    cudaFuncSetAttribute(gram_hmma, cudaFuncAttributeMaxDynamicSharedMemorySize, SMEM_DYN);

    cvt_kernel<<<(Bn * Ln * (Dn / 4)) / 256, 256>>>(H, W);

    dim3 grid(NPAIR, Bn, 2);
    gram_hmma<<<grid, 256, SMEM_DYN>>>(bias, out);
}

// round 4
// speedup vs baseline: 2.6352x; 1.1522x over previous
#include <cuda_runtime.h>
#include <cuda_bf16.h>
#include <cstdint>

static constexpr int Bn = 2;
static constexpr int Ln = 2048;
static constexpr int Dn = 1536;
static constexpr int NTILE = Ln / 128;                 // 16
static constexpr int NPAIR = NTILE * (NTILE + 1) / 2;  // 136
static constexpr int BK = 32;                          // k per stage
static constexpr int NSTG = Dn / BK;                   // 48
static constexpr int TILE_B = 128 * BK * 2;            // 8192 bytes per tile (swizzled, no pad)
static constexpr int NSTAGE = 3;
static constexpr int SMEM_DYN = NSTAGE * 4 * TILE_B;   // 98304 bytes

// bf16 planes: 0..7 = H*Wp_t split (b*4 + t*2 + {hi,lo}); 8..11 = H split (8 + b*2 + {hi,lo})
__device__ __align__(16) __nv_bfloat16 g_cvt[12ull * Ln * Dn];

// ---------------------------------------------------------------- convert
__global__ __launch_bounds__(256) void cvt_kernel(const float* __restrict__ H,
                                                  const float* __restrict__ W)
{
    const int idx = blockIdx.x * 256 + threadIdx.x;   // Bn*Ln*(Dn/4) total
    const int d4  = idx % (Dn / 4);
    const int row = (idx / (Dn / 4)) % Ln;
    const int b   = idx / ((Dn / 4) * Ln);
    const int d0  = d4 * 4;

    const float4 h = *reinterpret_cast<const float4*>(H + ((size_t)b * Ln + row) * Dn + d0);
    const size_t rowoff = (size_t)row * Dn + d0;

    auto store_split = [&](int plane_hi, float4 v) {
        float a[4] = {v.x, v.y, v.z, v.w};
        __nv_bfloat16 hi[4], lo[4];
#pragma unroll
        for (int i = 0; i < 4; ++i) {
            hi[i] = __float2bfloat16(a[i]);
            lo[i] = __float2bfloat16(a[i] - __bfloat162float(hi[i]));
        }
        __nv_bfloat162* ph = reinterpret_cast<__nv_bfloat162*>(
            g_cvt + (size_t)plane_hi * Ln * Dn + rowoff);
        __nv_bfloat162* pl = reinterpret_cast<__nv_bfloat162*>(
            g_cvt + (size_t)(plane_hi + 1) * Ln * Dn + rowoff);
        ph[0] = __nv_bfloat162(hi[0], hi[1]);
        ph[1] = __nv_bfloat162(hi[2], hi[3]);
        pl[0] = __nv_bfloat162(lo[0], lo[1]);
        pl[1] = __nv_bfloat162(lo[2], lo[3]);
    };

#pragma unroll
    for (int t = 0; t < 2; ++t) {
        const float4 w = *reinterpret_cast<const float4*>(W + (size_t)t * (2 * Dn) + d0);
        store_split(b * 4 + t * 2, make_float4(h.x * w.x, h.y * w.y, h.z * w.z, h.w * w.w));
    }
    store_split(8 + b * 2, h);
}

// ---------------------------------------------------------------- helpers
__device__ __forceinline__ uint32_t s2u(const void* p) {
    uint32_t a;
    asm("{ .reg .u64 t; cvta.to.shared.u64 t, %1; cvt.u32.u64 %0, t; }" : "=r"(a) : "l"(p));
    return a;
}

// swizzled byte offset inside an 128x32(bf16) tile: row*64 + (c ^ ((row>>1)&3))*16
__device__ __forceinline__ uint32_t swz(int row, int c) {
    return (uint32_t)(row * 64 + ((c ^ ((row >> 1) & 3)) << 4));
}

#define LDSM4(R0, R1, R2, R3, addr)                                            \
    asm volatile("ldmatrix.sync.aligned.m8n8.x4.shared.b16 {%0,%1,%2,%3}, [%4];" \
                 : "=r"(R0), "=r"(R1), "=r"(R2), "=r"(R3) : "r"(addr))

#define MMA(C, A, B)                                                              \
    asm volatile(                                                                 \
        "mma.sync.aligned.m16n8k16.row.col.f32.bf16.bf16.f32 "                    \
        "{%0,%1,%2,%3},{%4,%5,%6,%7},{%8,%9},{%0,%1,%2,%3};"                      \
        : "+f"((C)[0]), "+f"((C)[1]), "+f"((C)[2]), "+f"((C)[3])                  \
        : "r"((A)[0]), "r"((A)[1]), "r"((A)[2]), "r"((A)[3]),                     \
          "r"((B)[0]), "r"((B)[1]))

// ---------------------------------------------------------------- gram GEMM
__global__ __launch_bounds__(256, 2)
void gram_hmma(const float* __restrict__ bias, float* __restrict__ out)
{
    extern __shared__ __align__(1024) char smem_raw[];
    const uint32_t sb = s2u(smem_raw);

    const int tid = threadIdx.x;
    const int wid = tid >> 5;
    const int lane = tid & 31;

    // warp tile: 64x32; warp grid 2(m) x 4(n)
    const int wm = (wid >> 2) * 64;
    const int wn = (wid & 3) * 32;

    // ldmatrix lane address components
    const int a_row = lane & 15;            // m-row within 16
    const int ak3   = lane >> 4;            // k chunk bit (0/1)
    const int b_row = (lane & 7) + (lane >> 4) * 8;   // n-row within 16
    const int bk3   = (lane >> 3) & 1;      // k chunk bit (0/1)

    // decode upper-triangular tile pair
    int rem = blockIdx.x, ti = 0, rl = NTILE;
    while (rem >= rl) { rem -= rl; --rl; ++ti; }
    const int tj = ti + rem;
    const int b = blockIdx.y;
    const int t = blockIdx.z;
    const int gi0 = ti * 128, gj0 = tj * 128;

    const __nv_bfloat16* src[4];
    src[0] = g_cvt + ((size_t)(b * 4 + t * 2) * Ln + gi0) * Dn;      // A hi
    src[1] = src[0] + (size_t)Ln * Dn;                                // A lo
    src[2] = g_cvt + ((size_t)(8 + b * 2) * Ln + gj0) * Dn;           // B hi
    src[3] = src[2] + (size_t)Ln * Dn;                                // B lo

    // per-thread cp.async coords (2 chunks of 16B per tile)
    const int ld_row0 = tid >> 2, ld_c = tid & 3;

    auto load_stage = [&](int s, int buf) {
        const int k0 = s * BK;
        const uint32_t sbase = sb + buf * (4 * TILE_B);
#pragma unroll
        for (int tI = 0; tI < 4; ++tI) {
            const __nv_bfloat16* base = src[tI] + k0;
            const uint32_t tb = sbase + tI * TILE_B;
#pragma unroll
            for (int c2 = 0; c2 < 2; ++c2) {
                const int row = ld_row0 + c2 * 64;
                const uint32_t d = tb + swz(row, ld_c);
                const void* g = base + (size_t)row * Dn + ld_c * 8;
                asm volatile("cp.async.cg.shared.global [%0], [%1], 16;"
                             :: "r"(d), "l"(g) : "memory");
            }
        }
        asm volatile("cp.async.commit_group;" ::: "memory");
    };

    float acc[4][4][4];
#pragma unroll
    for (int mt = 0; mt < 4; ++mt)
#pragma unroll
        for (int nt = 0; nt < 4; ++nt)
#pragma unroll
            for (int e = 0; e < 4; ++e) acc[mt][nt][e] = 0.f;

    load_stage(0, 0);
    load_stage(1, 1);

#pragma unroll 1
    for (int s = 0; s < NSTG; ++s) {
        const int buf = s % NSTAGE;
        asm volatile("cp.async.wait_group 1;" ::: "memory");
        __syncthreads();
        if (s + 2 < NSTG) load_stage(s + 2, (s + 2) % NSTAGE);

        const uint32_t Ah = sb + (buf * 4 + 0) * TILE_B;
        const uint32_t Al = sb + (buf * 4 + 1) * TILE_B;
        const uint32_t Bh = sb + (buf * 4 + 2) * TILE_B;
        const uint32_t Bl = sb + (buf * 4 + 3) * TILE_B;

#pragma unroll
        for (int s16 = 0; s16 < 2; ++s16) {
            const int ca = s16 * 2 + ak3;   // A k-chunk
            const int cb = s16 * 2 + bk3;   // B k-chunk

            uint32_t bh[4][2], bl[4][2];
#pragma unroll
            for (int n2 = 0; n2 < 2; ++n2) {
                const int rB = wn + n2 * 16 + b_row;
                uint32_t addr = Bh + swz(rB, cb);
                LDSM4(bh[n2 * 2][0], bh[n2 * 2][1], bh[n2 * 2 + 1][0], bh[n2 * 2 + 1][1], addr);
                addr = Bl + swz(rB, cb);
                LDSM4(bl[n2 * 2][0], bl[n2 * 2][1], bl[n2 * 2 + 1][0], bl[n2 * 2 + 1][1], addr);
            }

            {
                uint32_t ah[4][4];
#pragma unroll
                for (int mt = 0; mt < 4; ++mt) {
                    const int rA = wm + mt * 16 + a_row;
                    LDSM4(ah[mt][0], ah[mt][1], ah[mt][2], ah[mt][3], Ah + swz(rA, ca));
                }
#pragma unroll
                for (int mt = 0; mt < 4; ++mt)
#pragma unroll
                    for (int nt = 0; nt < 4; ++nt) {
                        MMA(acc[mt][nt], ah[mt], bh[nt]);
                        MMA(acc[mt][nt], ah[mt], bl[nt]);
                    }
            }
            {
                uint32_t al[4][4];
#pragma unroll
                for (int mt = 0; mt < 4; ++mt) {
                    const int rA = wm + mt * 16 + a_row;
                    LDSM4(al[mt][0], al[mt][1], al[mt][2], al[mt][3], Al + swz(rA, ca));
                }
#pragma unroll
                for (int mt = 0; mt < 4; ++mt)
#pragma unroll
                    for (int nt = 0; nt < 4; ++nt)
                        MMA(acc[mt][nt], al[mt], bh[nt]);
            }
        }
    }

    // ------------------------------------------------------------ epilogue
    const float bt = __ldg(&bias[t]);
    float* o = out + ((size_t)b * Ln * Ln) * 2 + t;
    const int r4 = lane >> 2;
    const int c4 = (lane & 3) * 2;
    const bool mirror = (ti != tj);

#pragma unroll
    for (int mt = 0; mt < 4; ++mt) {
#pragma unroll
        for (int nt = 0; nt < 4; ++nt) {
            const int i0 = gi0 + wm + mt * 16 + r4;
            const int j0 = gj0 + wn + nt * 8 + c4;
            const float v0 = acc[mt][nt][0] + bt;
            const float v1 = acc[mt][nt][1] + bt;
            const float v2 = acc[mt][nt][2] + bt;
            const float v3 = acc[mt][nt][3] + bt;
            o[((size_t)i0 * Ln + j0) * 2]           = v0;
            o[((size_t)i0 * Ln + j0 + 1) * 2]       = v1;
            o[((size_t)(i0 + 8) * Ln + j0) * 2]     = v2;
            o[((size_t)(i0 + 8) * Ln + j0 + 1) * 2] = v3;
            if (mirror) {
                o[((size_t)j0 * Ln + i0) * 2]           = v0;
                o[((size_t)(j0 + 1) * Ln + i0) * 2]     = v1;
                o[((size_t)j0 * Ln + i0 + 8) * 2]       = v2;
                o[((size_t)(j0 + 1) * Ln + i0 + 8) * 2] = v3;
            }
        }
    }
}

// ---------------------------------------------------------------- launch
extern "C" void kernel_launch(void* const* d_in, const int* in_sizes, int n_in,
                              void* d_out, int out_size)
{
    const float* H    = (const float*)d_in[0];
    const float* W    = (const float*)d_in[1];
    const float* bias = (const float*)d_in[2];
    float* out = (float*)d_out;

    cudaFuncSetAttribute(gram_hmma, cudaFuncAttributeMaxDynamicSharedMemorySize, SMEM_DYN);

    cvt_kernel<<<(Bn * Ln * (Dn / 4)) / 256, 256>>>(H, W);

    dim3 grid(NPAIR, Bn, 2);
    gram_hmma<<<grid, 256, SMEM_DYN>>>(bias, out);
}

// round 5
// speedup vs baseline: 2.6451x; 1.0038x over previous
#include <cuda_runtime.h>
#include <cuda_bf16.h>
#include <cstdint>

static constexpr int Bn = 2;
static constexpr int Ln = 2048;
static constexpr int Dn = 1536;
static constexpr int NTILE = Ln / 128;                 // 16
static constexpr int NPAIR = NTILE * (NTILE + 1) / 2;  // 136
static constexpr int BK = 32;                          // k per stage
static constexpr int NSTG = Dn / BK;                   // 48
static constexpr int TILE_B = 128 * BK * 2;            // 8192 bytes per tile (swizzled)
static constexpr int NSTAGE = 3;
static constexpr int SMEM_DYN = NSTAGE * 4 * TILE_B;   // 98304 bytes

// bf16 planes: 0..7 = H*Wp_t split (b*4 + t*2 + {hi,lo}); 8..11 = H split (8 + b*2 + {hi,lo})
__device__ __align__(16) __nv_bfloat16 g_cvt[12ull * Ln * Dn];

// ---------------------------------------------------------------- convert
__global__ __launch_bounds__(256) void cvt_kernel(const float* __restrict__ H,
                                                  const float* __restrict__ W)
{
    const int idx = blockIdx.x * 256 + threadIdx.x;   // Bn*Ln*(Dn/4) total
    const int d4  = idx % (Dn / 4);
    const int row = (idx / (Dn / 4)) % Ln;
    const int b   = idx / ((Dn / 4) * Ln);
    const int d0  = d4 * 4;

    const float4 h = *reinterpret_cast<const float4*>(H + ((size_t)b * Ln + row) * Dn + d0);
    const size_t rowoff = (size_t)row * Dn + d0;

    auto store_split = [&](int plane_hi, float4 v) {
        float a[4] = {v.x, v.y, v.z, v.w};
        __nv_bfloat16 hi[4], lo[4];
#pragma unroll
        for (int i = 0; i < 4; ++i) {
            hi[i] = __float2bfloat16(a[i]);
            lo[i] = __float2bfloat16(a[i] - __bfloat162float(hi[i]));
        }
        __nv_bfloat162* ph = reinterpret_cast<__nv_bfloat162*>(
            g_cvt + (size_t)plane_hi * Ln * Dn + rowoff);
        __nv_bfloat162* pl = reinterpret_cast<__nv_bfloat162*>(
            g_cvt + (size_t)(plane_hi + 1) * Ln * Dn + rowoff);
        ph[0] = __nv_bfloat162(hi[0], hi[1]);
        ph[1] = __nv_bfloat162(hi[2], hi[3]);
        pl[0] = __nv_bfloat162(lo[0], lo[1]);
        pl[1] = __nv_bfloat162(lo[2], lo[3]);
    };

#pragma unroll
    for (int t = 0; t < 2; ++t) {
        const float4 w = *reinterpret_cast<const float4*>(W + (size_t)t * (2 * Dn) + d0);
        store_split(b * 4 + t * 2, make_float4(h.x * w.x, h.y * w.y, h.z * w.z, h.w * w.w));
    }
    store_split(8 + b * 2, h);
}

// ---------------------------------------------------------------- helpers
__device__ __forceinline__ uint32_t s2u(const void* p) {
    uint32_t a;
    asm("{ .reg .u64 t; cvta.to.shared.u64 t, %1; cvt.u32.u64 %0, t; }" : "=r"(a) : "l"(p));
    return a;
}

// swizzled byte offset inside a 128x32(bf16) tile: row*64 + (c ^ ((row>>1)&3))*16
__device__ __forceinline__ uint32_t swz(int row, int c) {
    return (uint32_t)(row * 64 + ((c ^ ((row >> 1) & 3)) << 4));
}

#define LDSM4(R0, R1, R2, R3, addr)                                            \
    asm volatile("ldmatrix.sync.aligned.m8n8.x4.shared.b16 {%0,%1,%2,%3}, [%4];" \
                 : "=r"(R0), "=r"(R1), "=r"(R2), "=r"(R3) : "r"(addr))

#define MMA(C, A, B)                                                              \
    asm volatile(                                                                 \
        "mma.sync.aligned.m16n8k16.row.col.f32.bf16.bf16.f32 "                    \
        "{%0,%1,%2,%3},{%4,%5,%6,%7},{%8,%9},{%0,%1,%2,%3};"                      \
        : "+f"((C)[0]), "+f"((C)[1]), "+f"((C)[2]), "+f"((C)[3])                  \
        : "r"((A)[0]), "r"((A)[1]), "r"((A)[2]), "r"((A)[3]),                     \
          "r"((B)[0]), "r"((B)[1]))

// ---------------------------------------------------------------- gram GEMM
__global__ __launch_bounds__(256, 2)
void gram_hmma(const float* __restrict__ bias, float* __restrict__ out)
{
    extern __shared__ __align__(1024) char smem_raw[];
    const uint32_t sb = s2u(smem_raw);

    const int tid = threadIdx.x;
    const int wid = tid >> 5;
    const int lane = tid & 31;

    // warp tile: 64x32; warp grid 2(m) x 4(n)
    const int wm = (wid >> 2) * 64;
    const int wn = (wid & 3) * 32;

    // ldmatrix lane address components
    const int a_row = lane & 15;
    const int ak3   = lane >> 4;
    const int b_row = (lane & 7) + (lane >> 4) * 8;
    const int bk3   = (lane >> 3) & 1;

    // decode upper-triangular tile pair
    int rem = blockIdx.x, ti = 0, rl = NTILE;
    while (rem >= rl) { rem -= rl; --rl; ++ti; }
    const int tj = ti + rem;
    const int b = blockIdx.y;
    const int t = blockIdx.z;
    const int gi0 = ti * 128, gj0 = tj * 128;

    const __nv_bfloat16* src[4];
    src[0] = g_cvt + ((size_t)(b * 4 + t * 2) * Ln + gi0) * Dn;      // A hi
    src[1] = src[0] + (size_t)Ln * Dn;                                // A lo
    src[2] = g_cvt + ((size_t)(8 + b * 2) * Ln + gj0) * Dn;           // B hi
    src[3] = src[2] + (size_t)Ln * Dn;                                // B lo

    const int ld_row0 = tid >> 2, ld_c = tid & 3;

    auto load_stage = [&](int s, int buf) {
        const int k0 = s * BK;
        const uint32_t sbase = sb + buf * (4 * TILE_B);
#pragma unroll
        for (int tI = 0; tI < 4; ++tI) {
            const __nv_bfloat16* base = src[tI] + k0;
            const uint32_t tb = sbase + tI * TILE_B;
#pragma unroll
            for (int c2 = 0; c2 < 2; ++c2) {
                const int row = ld_row0 + c2 * 64;
                const uint32_t d = tb + swz(row, ld_c);
                const void* g = base + (size_t)row * Dn + ld_c * 8;
                asm volatile("cp.async.cg.shared.global [%0], [%1], 16;"
                             :: "r"(d), "l"(g) : "memory");
            }
        }
        asm volatile("cp.async.commit_group;" ::: "memory");
    };

    float acc[4][4][4];
#pragma unroll
    for (int mt = 0; mt < 4; ++mt)
#pragma unroll
        for (int nt = 0; nt < 4; ++nt)
#pragma unroll
            for (int e = 0; e < 4; ++e) acc[mt][nt][e] = 0.f;

    load_stage(0, 0);
    load_stage(1, 1);

#pragma unroll 1
    for (int s = 0; s < NSTG; ++s) {
        const int buf = s % NSTAGE;
        asm volatile("cp.async.wait_group 1;" ::: "memory");
        __syncthreads();
        if (s + 2 < NSTG) load_stage(s + 2, (s + 2) % NSTAGE);

        const uint32_t Ah = sb + (buf * 4 + 0) * TILE_B;
        const uint32_t Al = sb + (buf * 4 + 1) * TILE_B;
        const uint32_t Bh = sb + (buf * 4 + 2) * TILE_B;
        const uint32_t Bl = sb + (buf * 4 + 3) * TILE_B;

#pragma unroll
        for (int s16 = 0; s16 < 2; ++s16) {
            const int ca = s16 * 2 + ak3;   // A k-chunk
            const int cb = s16 * 2 + bk3;   // B k-chunk

            // ---- load all fragments for this k16 up front
            uint32_t bh[4][2], bl[4][2];
#pragma unroll
            for (int n2 = 0; n2 < 2; ++n2) {
                const int rB = wn + n2 * 16 + b_row;
                uint32_t addr = Bh + swz(rB, cb);
                LDSM4(bh[n2 * 2][0], bh[n2 * 2][1], bh[n2 * 2 + 1][0], bh[n2 * 2 + 1][1], addr);
                addr = Bl + swz(rB, cb);
                LDSM4(bl[n2 * 2][0], bl[n2 * 2][1], bl[n2 * 2 + 1][0], bl[n2 * 2 + 1][1], addr);
            }
            uint32_t ah[4][4];
#pragma unroll
            for (int mt = 0; mt < 4; ++mt) {
                const int rA = wm + mt * 16 + a_row;
                LDSM4(ah[mt][0], ah[mt][1], ah[mt][2], ah[mt][3], Ah + swz(rA, ca));
            }

            // ---- block 1: 16 independent MMAs (ah x bh)
#pragma unroll
            for (int nt = 0; nt < 4; ++nt)
#pragma unroll
                for (int mt = 0; mt < 4; ++mt)
                    MMA(acc[mt][nt], ah[mt], bh[nt]);

            // ---- block 2: 16 independent MMAs (ah x bl), reuse ah
#pragma unroll
            for (int nt = 0; nt < 4; ++nt)
#pragma unroll
                for (int mt = 0; mt < 4; ++mt)
                    MMA(acc[mt][nt], ah[mt], bl[nt]);

            // ---- block 3: load al, 16 independent MMAs (al x bh)
            uint32_t al[4][4];
#pragma unroll
            for (int mt = 0; mt < 4; ++mt) {
                const int rA = wm + mt * 16 + a_row;
                LDSM4(al[mt][0], al[mt][1], al[mt][2], al[mt][3], Al + swz(rA, ca));
            }
#pragma unroll
            for (int nt = 0; nt < 4; ++nt)
#pragma unroll
                for (int mt = 0; mt < 4; ++mt)
                    MMA(acc[mt][nt], al[mt], bh[nt]);
        }
    }

    // ------------------------------------------------------------ epilogue
    const float bt = __ldg(&bias[t]);
    float* o = out + ((size_t)b * Ln * Ln) * 2 + t;
    const int r4 = lane >> 2;
    const int c4 = (lane & 3) * 2;
    const bool mirror = (ti != tj);

#pragma unroll
    for (int mt = 0; mt < 4; ++mt) {
#pragma unroll
        for (int nt = 0; nt < 4; ++nt) {
            const int i0 = gi0 + wm + mt * 16 + r4;
            const int j0 = gj0 + wn + nt * 8 + c4;
            const float v0 = acc[mt][nt][0] + bt;
            const float v1 = acc[mt][nt][1] + bt;
            const float v2 = acc[mt][nt][2] + bt;
            const float v3 = acc[mt][nt][3] + bt;
            o[((size_t)i0 * Ln + j0) * 2]           = v0;
            o[((size_t)i0 * Ln + j0 + 1) * 2]       = v1;
            o[((size_t)(i0 + 8) * Ln + j0) * 2]     = v2;
            o[((size_t)(i0 + 8) * Ln + j0 + 1) * 2] = v3;
            if (mirror) {
                o[((size_t)j0 * Ln + i0) * 2]           = v0;
                o[((size_t)(j0 + 1) * Ln + i0) * 2]     = v1;
                o[((size_t)j0 * Ln + i0 + 8) * 2]       = v2;
                o[((size_t)(j0 + 1) * Ln + i0 + 8) * 2] = v3;
            }
        }
    }
}

// ---------------------------------------------------------------- launch
extern "C" void kernel_launch(void* const* d_in, const int* in_sizes, int n_in,
                              void* d_out, int out_size)
{
    const float* H    = (const float*)d_in[0];
    const float* W    = (const float*)d_in[1];
    const float* bias = (const float*)d_in[2];
    float* out = (float*)d_out;

    cudaFuncSetAttribute(gram_hmma, cudaFuncAttributeMaxDynamicSharedMemorySize, SMEM_DYN);

    cvt_kernel<<<(Bn * Ln * (Dn / 4)) / 256, 256>>>(H, W);

    dim3 grid(NPAIR, Bn, 2);
    gram_hmma<<<grid, 256, SMEM_DYN>>>(bias, out);
}